// round 8
// baseline (speedup 1.0000x reference)
#include <cuda_runtime.h>
#include <cuda_bf16.h>
#include <math.h>

#define BB   4
#define HH   12
#define TT   2048
#define DD   64
#define PP   768
#define SCALE 0.125f

typedef unsigned long long ull;

__device__ float g_q[BB * HH * TT * DD];
__device__ float g_k[BB * HH * TT * DD];
__device__ float g_v[BB * HH * TT * DD];

__device__ __forceinline__ ull pack2(float lo, float hi) {
    ull r;
    asm("mov.b64 %0, {%1, %2};" : "=l"(r) : "f"(lo), "f"(hi));
    return r;
}
__device__ __forceinline__ void unpack2(ull v, float& lo, float& hi) {
    asm("mov.b64 {%0, %1}, %2;" : "=f"(lo), "=f"(hi) : "l"(v));
}
__device__ __forceinline__ ull fma2(ull a, ull b, ull c) {
    ull d;
    asm("fma.rn.f32x2 %0, %1, %2, %3;" : "=l"(d) : "l"(a), "l"(b), "l"(c));
    return d;
}
__device__ __forceinline__ ull mul2(ull a, ull b) {
    ull d;
    asm("mul.rn.f32x2 %0, %1, %2;" : "=l"(d) : "l"(a), "l"(b));
    return d;
}

// ---------------------------------------------------------------------------
// Kernel 1: QKV projection (~85us, ~5% of runtime)
// ---------------------------------------------------------------------------
__global__ __launch_bounds__(128)
void qkv_proj_kernel(const float* __restrict__ X,
                     const float* __restrict__ Wq, const float* __restrict__ bq,
                     const float* __restrict__ Wk, const float* __restrict__ bk,
                     const float* __restrict__ Wv, const float* __restrict__ bv) {
    __shared__ float Xs[64][68];
    __shared__ float Ws[64][64];

    const int rt = blockIdx.x;
    const int h  = blockIdx.y;
    const int z  = blockIdx.z;

    const float* W    = (z == 0) ? Wq : (z == 1) ? Wk : Wv;
    const float* bias = (z == 0) ? bq : (z == 1) ? bk : bv;
    float* out        = (z == 0) ? g_q : (z == 1) ? g_k : g_v;

    const int tid = threadIdx.x;
    const int ty = tid >> 3;
    const int tx = tid & 7;

    #pragma unroll
    for (int i = 0; i < 8; i++) {
        int lin = i * 512 + tid * 4;
        int rr = lin >> 6, kk = lin & 63;
        float4 xv = *(const float4*)(X + (size_t)(rt * 64 + rr) * 64 + kk);
        *(float4*)&Xs[rr][kk] = xv;
        float4 wv = *(const float4*)(W + (size_t)(lin >> 6) * PP + h * 64 + (lin & 63));
        *(float4*)&Ws[lin >> 6][lin & 63] = wv;
    }
    __syncthreads();

    float acc[4][8];
    #pragma unroll
    for (int i = 0; i < 4; i++)
        #pragma unroll
        for (int j = 0; j < 8; j++) acc[i][j] = 0.0f;

    #pragma unroll 4
    for (int k = 0; k < 64; k++) {
        float a[4];
        #pragma unroll
        for (int i = 0; i < 4; i++) a[i] = Xs[ty * 4 + i][k];
        float b[8];
        float4 b0 = *(float4*)&Ws[k][tx * 8];
        float4 b1 = *(float4*)&Ws[k][tx * 8 + 4];
        b[0]=b0.x; b[1]=b0.y; b[2]=b0.z; b[3]=b0.w;
        b[4]=b1.x; b[5]=b1.y; b[6]=b1.z; b[7]=b1.w;
        #pragma unroll
        for (int i = 0; i < 4; i++)
            #pragma unroll
            for (int j = 0; j < 8; j++) acc[i][j] += a[i] * b[j];
    }

    float bb[8];
    #pragma unroll
    for (int j = 0; j < 8; j++) bb[j] = bias[h * 64 + tx * 8 + j];

    #pragma unroll
    for (int i = 0; i < 4; i++) {
        int r = rt * 64 + ty * 4 + i;
        int bidx = r >> 11;
        int t    = r & 2047;
        float* dst = out + (((size_t)(bidx * HH + h)) * TT + t) * DD + tx * 8;
        float4 o0 = make_float4(acc[i][0]+bb[0], acc[i][1]+bb[1], acc[i][2]+bb[2], acc[i][3]+bb[3]);
        float4 o1 = make_float4(acc[i][4]+bb[4], acc[i][5]+bb[5], acc[i][6]+bb[6], acc[i][7]+bb[7]);
        *(float4*)(dst)     = o0;
        *(float4*)(dst + 4) = o1;
    }
}

// ---------------------------------------------------------------------------
// Kernel 2: flash attention.
//   256 threads; ty=tid>>4 (8 query rows each), tx=tid&15.
//   Score columns per thread: {2tx, 2tx+1, 32+2tx, 33+2tx}.
//   Output d-cols per thread: {4tx..4tx+3}.
//   Layouts:
//     Qs ull [32 kp][130] : (Q[r][2kp],Q[r][2kp+1]) pre-scaled  (33.3KB)
//     Ks ull [32 kp][66]  : (K[c][2kp],K[c][2kp+1])             (16.9KB)
//     Psf f32 [128 r][68] : plain row-major P (conflict-free 8B stores) (34.8KB)
//     Vs  f32 [64 c][68]  : plain row-major V                   (17.4KB)
//     ms  f32 [64]
//   GEMM2 packs over c-pairs: acc lo=even-c partial, hi=odd-c partial.
// ---------------------------------------------------------------------------
#define QS_STRIDE 130
#define KS_STRIDE 66
#define PS_STRIDE 68
#define VS_STRIDE 68
#define FLASH_SMEM ((32*QS_STRIDE + 32*KS_STRIDE) * 8 + (128*PS_STRIDE + 64*VS_STRIDE) * 4 + 256)

__global__ __launch_bounds__(256)
void flash_attn_kernel(const float* __restrict__ mask, float* __restrict__ out) {
    extern __shared__ ull sm[];
    ull*   Qs  = sm;                             // [32][130] ull
    ull*   Ks  = Qs + 32 * QS_STRIDE;            // [32][66]  ull
    float* Psf = (float*)(Ks + 32 * KS_STRIDE);  // [128][68] f32
    float* Vs  = Psf + 128 * PS_STRIDE;          // [64][68]  f32
    float* ms  = Vs + 64 * VS_STRIDE;            // [64]      f32

    const int qt = blockIdx.x;
    const int bh = blockIdx.y;
    const int b  = bh / HH;
    const int h  = bh % HH;
    const int tid = threadIdx.x;
    const int ty = tid >> 4;                     // 0..15
    const int tx = tid & 15;                     // 0..15

    const float* qg = g_q + (size_t)bh * TT * DD + (size_t)qt * 128 * DD;
    const float* kg = g_k + (size_t)bh * TT * DD;
    const float* vg = g_v + (size_t)bh * TT * DD;

    const int lrow = tid >> 4;
    const int lcol = (tid & 15) * 4;

    // Load Q tile (128x64), scaled, k-pair-major: Qs[kp][r]
    #pragma unroll
    for (int i = 0; i < 8; i++) {
        int r = lrow + i * 16;
        float4 v = *(const float4*)(qg + (size_t)r * DD + lcol);
        int kp = lcol >> 1;
        Qs[(kp    ) * QS_STRIDE + r] = pack2(v.x * SCALE, v.y * SCALE);
        Qs[(kp + 1) * QS_STRIDE + r] = pack2(v.z * SCALE, v.w * SCALE);
    }

    float m_i[8], l_i[8];
    ull o2[8][4];                                // lo: even-c partial, hi: odd-c
    #pragma unroll
    for (int i = 0; i < 8; i++) {
        m_i[i] = -INFINITY;
        l_i[i] = 0.0f;
        #pragma unroll
        for (int j = 0; j < 4; j++) o2[i][j] = 0ull;
    }

    // Prefetch K/V tile 0 into registers
    float4 kpre[4], vpre[4];
    #pragma unroll
    for (int i = 0; i < 4; i++) {
        int c = lrow + i * 16;
        kpre[i] = *(const float4*)(kg + (size_t)c * DD + lcol);
        vpre[i] = *(const float4*)(vg + (size_t)c * DD + lcol);
    }

    for (int kt = 0; kt < TT / 64; kt++) {
        __syncthreads();

        // Store K tile: Ks[kp][c] pairs
        #pragma unroll
        for (int i = 0; i < 4; i++) {
            int c = lrow + i * 16;
            int kp = lcol >> 1;
            float4 v = kpre[i];
            Ks[(kp    ) * KS_STRIDE + c] = pack2(v.x, v.y);
            Ks[(kp + 1) * KS_STRIDE + c] = pack2(v.z, v.w);
        }
        // Store V tile: plain row-major float4 (conflict-free)
        #pragma unroll
        for (int i = 0; i < 4; i++) {
            int c = lrow + i * 16;
            *(float4*)(Vs + c * VS_STRIDE + lcol) = vpre[i];
        }
        if (tid < 64)
            ms[tid] = (1.0f - mask[(size_t)b * TT + kt * 64 + tid]) * -10000.0f;
        __syncthreads();

        // GEMM1: S = Q K^T (f32x2-packed over k-pairs)
        ull s2[8][4];
        #pragma unroll
        for (int i = 0; i < 8; i++)
            #pragma unroll
            for (int j = 0; j < 4; j++) s2[i][j] = 0ull;

        #pragma unroll 4
        for (int kp = 0; kp < 32; kp++) {
            const ull* qrow = Qs + kp * QS_STRIDE + ty * 8;
            const ull* krow = Ks + kp * KS_STRIDE;
            ull a[8], bf[4];
            ulonglong2 t0 = *(const ulonglong2*)(qrow);
            ulonglong2 t1 = *(const ulonglong2*)(qrow + 2);
            ulonglong2 t2 = *(const ulonglong2*)(qrow + 4);
            ulonglong2 t3 = *(const ulonglong2*)(qrow + 6);
            a[0]=t0.x; a[1]=t0.y; a[2]=t1.x; a[3]=t1.y;
            a[4]=t2.x; a[5]=t2.y; a[6]=t3.x; a[7]=t3.y;
            ulonglong2 u0 = *(const ulonglong2*)(krow + 2 * tx);
            ulonglong2 u1 = *(const ulonglong2*)(krow + 32 + 2 * tx);
            bf[0]=u0.x; bf[1]=u0.y; bf[2]=u1.x; bf[3]=u1.y;
            #pragma unroll
            for (int i = 0; i < 8; i++)
                #pragma unroll
                for (int j = 0; j < 4; j++)
                    s2[i][j] = fma2(a[i], bf[j], s2[i][j]);
        }

        // online softmax; columns c0..c3 = 2tx,2tx+1,32+2tx,33+2tx
        const float m0 = ms[2 * tx], m1 = ms[2 * tx + 1];
        const float m2 = ms[32 + 2 * tx], m3 = ms[33 + 2 * tx];
        #pragma unroll
        for (int i = 0; i < 8; i++) {
            float s[4];
            float lo, hi;
            unpack2(s2[i][0], lo, hi); s[0] = lo + hi + m0;
            unpack2(s2[i][1], lo, hi); s[1] = lo + hi + m1;
            unpack2(s2[i][2], lo, hi); s[2] = lo + hi + m2;
            unpack2(s2[i][3], lo, hi); s[3] = lo + hi + m3;

            float tmax = fmaxf(fmaxf(s[0], s[1]), fmaxf(s[2], s[3]));
            #pragma unroll
            for (int off = 1; off < 16; off <<= 1)
                tmax = fmaxf(tmax, __shfl_xor_sync(0xffffffffu, tmax, off));

            float mnew  = fmaxf(m_i[i], tmax);
            float alpha = __expf(m_i[i] - mnew);
            float p0 = __expf(s[0] - mnew);
            float p1 = __expf(s[1] - mnew);
            float p2 = __expf(s[2] - mnew);
            float p3 = __expf(s[3] - mnew);
            l_i[i] = l_i[i] * alpha + (p0 + p1) + (p2 + p3);
            m_i[i] = mnew;
            ull a2 = pack2(alpha, alpha);
            #pragma unroll
            for (int j = 0; j < 4; j++) o2[i][j] = mul2(o2[i][j], a2);

            // Conflict-free P stores: row-major, 8B each.
            int r = ty * 8 + i;
            *(ull*)(Psf + r * PS_STRIDE + 2 * tx)      = pack2(p0, p1);
            *(ull*)(Psf + r * PS_STRIDE + 32 + 2 * tx) = pack2(p2, p3);
        }

        // Prefetch next K/V tile (hidden behind barrier + GEMM2)
        if (kt + 1 < TT / 64) {
            const float* kn = kg + (size_t)(kt + 1) * 64 * DD;
            const float* vn = vg + (size_t)(kt + 1) * 64 * DD;
            #pragma unroll
            for (int i = 0; i < 4; i++) {
                int c = lrow + i * 16;
                kpre[i] = *(const float4*)(kn + (size_t)c * DD + lcol);
                vpre[i] = *(const float4*)(vn + (size_t)c * DD + lcol);
            }
        }
        __syncthreads();

        // GEMM2: O += P V, f32x2-packed over c-pairs.
        //   a = (p[r][2cp], p[r][2cp+1])  broadcast LDS.64
        //   b = (V[2cp][d], V[2cp+1][d])  packed from two contiguous LDS.128
        #pragma unroll 2
        for (int cp = 0; cp < 32; cp++) {
            float4 va = *(const float4*)(Vs + (2 * cp    ) * VS_STRIDE + 4 * tx);
            float4 vb = *(const float4*)(Vs + (2 * cp + 1) * VS_STRIDE + 4 * tx);
            ull v0 = pack2(va.x, vb.x);
            ull v1 = pack2(va.y, vb.y);
            ull v2 = pack2(va.z, vb.z);
            ull v3 = pack2(va.w, vb.w);
            const float* prow = Psf + (ty * 8) * PS_STRIDE + 2 * cp;
            #pragma unroll
            for (int i = 0; i < 8; i++) {
                ull pp = *(const ull*)(prow + i * PS_STRIDE);
                o2[i][0] = fma2(pp, v0, o2[i][0]);
                o2[i][1] = fma2(pp, v1, o2[i][1]);
                o2[i][2] = fma2(pp, v2, o2[i][2]);
                o2[i][3] = fma2(pp, v3, o2[i][3]);
            }
        }
    }

    // Epilogue: fold even/odd-c partials, reduce l over 16 lanes, scale, store.
    #pragma unroll
    for (int i = 0; i < 8; i++) {
        float lsum = l_i[i];
        #pragma unroll
        for (int off = 1; off < 16; off <<= 1)
            lsum += __shfl_xor_sync(0xffffffffu, lsum, off);
        float inv = 1.0f / lsum;
        float res[4];
        #pragma unroll
        for (int j = 0; j < 4; j++) {
            float lo, hi;
            unpack2(o2[i][j], lo, hi);
            res[j] = (lo + hi) * inv;
        }
        int r = ty * 8 + i;
        int t = qt * 128 + r;
        float4 v4 = make_float4(res[0], res[1], res[2], res[3]);
        *(float4*)(out + ((size_t)(b * TT + t)) * PP + h * 64 + 4 * tx) = v4;
    }
}

// ---------------------------------------------------------------------------
extern "C" void kernel_launch(void* const* d_in, const int* in_sizes, int n_in,
                              void* d_out, int out_size) {
    const float* hs   = (const float*)d_in[0];
    const float* mask = (const float*)d_in[1];
    const float* Wq   = (const float*)d_in[2];
    const float* bq   = (const float*)d_in[3];
    const float* Wk   = (const float*)d_in[4];
    const float* bk   = (const float*)d_in[5];
    const float* Wv   = (const float*)d_in[6];
    const float* bv   = (const float*)d_in[7];
    float* out = (float*)d_out;

    qkv_proj_kernel<<<dim3((BB * TT) / 64, HH, 3), 128>>>(hs, Wq, bq, Wk, bk, Wv, bv);

    cudaFuncSetAttribute(flash_attn_kernel,
                         cudaFuncAttributeMaxDynamicSharedMemorySize, FLASH_SMEM);
    flash_attn_kernel<<<dim3(TT / 128, BB * HH), 256, FLASH_SMEM>>>(mask, out);
}

// round 9
// speedup vs baseline: 1.1600x; 1.1600x over previous
#include <cuda_runtime.h>
#include <cuda_bf16.h>
#include <math.h>

#define BB   4
#define HH   12
#define TT   2048
#define DD   64
#define PP   768
#define SCALE 0.125f

typedef unsigned long long ull;

__device__ float g_q[BB * HH * TT * DD];
__device__ float g_k[BB * HH * TT * DD];
__device__ float g_v[BB * HH * TT * DD];

__device__ __forceinline__ ull pack2(float lo, float hi) {
    ull r;
    asm("mov.b64 %0, {%1, %2};" : "=l"(r) : "f"(lo), "f"(hi));
    return r;
}
__device__ __forceinline__ void unpack2(ull v, float& lo, float& hi) {
    asm("mov.b64 {%0, %1}, %2;" : "=f"(lo), "=f"(hi) : "l"(v));
}
__device__ __forceinline__ ull fma2(ull a, ull b, ull c) {
    ull d;
    asm("fma.rn.f32x2 %0, %1, %2, %3;" : "=l"(d) : "l"(a), "l"(b), "l"(c));
    return d;
}
__device__ __forceinline__ ull mul2(ull a, ull b) {
    ull d;
    asm("mul.rn.f32x2 %0, %1, %2;" : "=l"(d) : "l"(a), "l"(b));
    return d;
}

// ---------------------------------------------------------------------------
// Kernel 1: QKV projection (~5% of runtime)
// ---------------------------------------------------------------------------
__global__ __launch_bounds__(128)
void qkv_proj_kernel(const float* __restrict__ X,
                     const float* __restrict__ Wq, const float* __restrict__ bq,
                     const float* __restrict__ Wk, const float* __restrict__ bk,
                     const float* __restrict__ Wv, const float* __restrict__ bv) {
    __shared__ float Xs[64][68];
    __shared__ float Ws[64][64];

    const int rt = blockIdx.x;
    const int h  = blockIdx.y;
    const int z  = blockIdx.z;

    const float* W    = (z == 0) ? Wq : (z == 1) ? Wk : Wv;
    const float* bias = (z == 0) ? bq : (z == 1) ? bk : bv;
    float* out        = (z == 0) ? g_q : (z == 1) ? g_k : g_v;

    const int tid = threadIdx.x;
    const int ty = tid >> 3;
    const int tx = tid & 7;

    #pragma unroll
    for (int i = 0; i < 8; i++) {
        int lin = i * 512 + tid * 4;
        int rr = lin >> 6, kk = lin & 63;
        float4 xv = *(const float4*)(X + (size_t)(rt * 64 + rr) * 64 + kk);
        *(float4*)&Xs[rr][kk] = xv;
        float4 wv = *(const float4*)(W + (size_t)(lin >> 6) * PP + h * 64 + (lin & 63));
        *(float4*)&Ws[lin >> 6][lin & 63] = wv;
    }
    __syncthreads();

    float acc[4][8];
    #pragma unroll
    for (int i = 0; i < 4; i++)
        #pragma unroll
        for (int j = 0; j < 8; j++) acc[i][j] = 0.0f;

    #pragma unroll 4
    for (int k = 0; k < 64; k++) {
        float a[4];
        #pragma unroll
        for (int i = 0; i < 4; i++) a[i] = Xs[ty * 4 + i][k];
        float b[8];
        float4 b0 = *(float4*)&Ws[k][tx * 8];
        float4 b1 = *(float4*)&Ws[k][tx * 8 + 4];
        b[0]=b0.x; b[1]=b0.y; b[2]=b0.z; b[3]=b0.w;
        b[4]=b1.x; b[5]=b1.y; b[6]=b1.z; b[7]=b1.w;
        #pragma unroll
        for (int i = 0; i < 4; i++)
            #pragma unroll
            for (int j = 0; j < 8; j++) acc[i][j] += a[i] * b[j];
    }

    float bb[8];
    #pragma unroll
    for (int j = 0; j < 8; j++) bb[j] = bias[h * 64 + tx * 8 + j];

    #pragma unroll
    for (int i = 0; i < 4; i++) {
        int r = rt * 64 + ty * 4 + i;
        int bidx = r >> 11;
        int t    = r & 2047;
        float* dst = out + (((size_t)(bidx * HH + h)) * TT + t) * DD + tx * 8;
        float4 o0 = make_float4(acc[i][0]+bb[0], acc[i][1]+bb[1], acc[i][2]+bb[2], acc[i][3]+bb[3]);
        float4 o1 = make_float4(acc[i][4]+bb[4], acc[i][5]+bb[5], acc[i][6]+bb[6], acc[i][7]+bb[7]);
        *(float4*)(dst)     = o0;
        *(float4*)(dst + 4) = o1;
    }
}

// ---------------------------------------------------------------------------
// Kernel 2: flash attention.
//   256 threads; ty=tid>>4 (8 query rows each), tx=tid&15.
//   Score columns per thread: {2tx, 2tx+1, 32+2tx, 33+2tx}.
//   Output d-cols per thread: {4tx..4tx+3}.
//   Layouts:
//     Qs  ull [32 kp][130] : (Q[r][2kp],Q[r][2kp+1]) pre-scaled   33.3KB
//     Ks  ull [32 kp][66]  : (K[c][2kp],K[c][2kp+1])              16.9KB
//     Psd ull [128 r][66]  : DUPLICATED pairs (p_c,p_c) row-major 67.6KB
//         (stores are 16B STS.128 at r*66+2tx -> bank-group (i+tx)%8,
//          conflict-free; GEMM2 reads natural ulonglong2 pairs)
//     Vs  f32 [64 c][68]   : plain row-major V                    17.4KB
//     ms  f32 [64]
//   GEMM2: d-pair accumulators o2[8][2]; ALL fma2 operands come directly
//   from aligned ulonglong2 LDS (no in-loop pack2 -> low ALU, per R8 lesson).
// ---------------------------------------------------------------------------
#define QS_STRIDE  130
#define KS_STRIDE  66
#define PSD_STRIDE 66
#define VS_STRIDE  68
#define FLASH_SMEM ((32*QS_STRIDE + 32*KS_STRIDE + 128*PSD_STRIDE) * 8 + 64*VS_STRIDE*4 + 256)

__global__ __launch_bounds__(256)
void flash_attn_kernel(const float* __restrict__ mask, float* __restrict__ out) {
    extern __shared__ ull sm[];
    ull*   Qs  = sm;                             // [32][130] ull
    ull*   Ks  = Qs + 32 * QS_STRIDE;            // [32][66]  ull
    ull*   Psd = Ks + 32 * KS_STRIDE;            // [128][66] ull
    float* Vs  = (float*)(Psd + 128 * PSD_STRIDE); // [64][68] f32
    float* ms  = Vs + 64 * VS_STRIDE;            // [64]      f32

    const int qt = blockIdx.x;
    const int bh = blockIdx.y;
    const int b  = bh / HH;
    const int h  = bh % HH;
    const int tid = threadIdx.x;
    const int ty = tid >> 4;                     // 0..15
    const int tx = tid & 15;                     // 0..15

    const float* qg = g_q + (size_t)bh * TT * DD + (size_t)qt * 128 * DD;
    const float* kg = g_k + (size_t)bh * TT * DD;
    const float* vg = g_v + (size_t)bh * TT * DD;

    const int lrow = tid >> 4;
    const int lcol = (tid & 15) * 4;

    // Load Q tile (128x64), scaled, k-pair-major: Qs[kp][r]
    #pragma unroll
    for (int i = 0; i < 8; i++) {
        int r = lrow + i * 16;
        float4 v = *(const float4*)(qg + (size_t)r * DD + lcol);
        int kp = lcol >> 1;
        Qs[(kp    ) * QS_STRIDE + r] = pack2(v.x * SCALE, v.y * SCALE);
        Qs[(kp + 1) * QS_STRIDE + r] = pack2(v.z * SCALE, v.w * SCALE);
    }

    float m_i[8], l_i[8];                        // l_i = per-lane partials
    ull o2[8][2];                                // 2 d-pairs = 4 output floats
    #pragma unroll
    for (int i = 0; i < 8; i++) {
        m_i[i] = -INFINITY;
        l_i[i] = 0.0f;
        o2[i][0] = 0ull; o2[i][1] = 0ull;
    }

    // Prefetch K/V tile 0 into registers
    float4 kpre[4], vpre[4];
    #pragma unroll
    for (int i = 0; i < 4; i++) {
        int c = lrow + i * 16;
        kpre[i] = *(const float4*)(kg + (size_t)c * DD + lcol);
        vpre[i] = *(const float4*)(vg + (size_t)c * DD + lcol);
    }

    for (int kt = 0; kt < TT / 64; kt++) {
        __syncthreads();

        // Store K tile: Ks[kp][c] pairs
        #pragma unroll
        for (int i = 0; i < 4; i++) {
            int c = lrow + i * 16;
            int kp = lcol >> 1;
            float4 v = kpre[i];
            Ks[(kp    ) * KS_STRIDE + c] = pack2(v.x, v.y);
            Ks[(kp + 1) * KS_STRIDE + c] = pack2(v.z, v.w);
        }
        // Store V tile: plain row-major float4 (conflict-free)
        #pragma unroll
        for (int i = 0; i < 4; i++) {
            int c = lrow + i * 16;
            *(float4*)(Vs + c * VS_STRIDE + lcol) = vpre[i];
        }
        if (tid < 64)
            ms[tid] = (1.0f - mask[(size_t)b * TT + kt * 64 + tid]) * -10000.0f;
        __syncthreads();

        // GEMM1: S = Q K^T (f32x2-packed over k-pairs)
        ull s2[8][4];
        #pragma unroll
        for (int i = 0; i < 8; i++)
            #pragma unroll
            for (int j = 0; j < 4; j++) s2[i][j] = 0ull;

        #pragma unroll 4
        for (int kp = 0; kp < 32; kp++) {
            const ull* qrow = Qs + kp * QS_STRIDE + ty * 8;
            const ull* krow = Ks + kp * KS_STRIDE;
            ull a[8], bf[4];
            ulonglong2 t0 = *(const ulonglong2*)(qrow);
            ulonglong2 t1 = *(const ulonglong2*)(qrow + 2);
            ulonglong2 t2 = *(const ulonglong2*)(qrow + 4);
            ulonglong2 t3 = *(const ulonglong2*)(qrow + 6);
            a[0]=t0.x; a[1]=t0.y; a[2]=t1.x; a[3]=t1.y;
            a[4]=t2.x; a[5]=t2.y; a[6]=t3.x; a[7]=t3.y;
            ulonglong2 u0 = *(const ulonglong2*)(krow + 2 * tx);
            ulonglong2 u1 = *(const ulonglong2*)(krow + 32 + 2 * tx);
            bf[0]=u0.x; bf[1]=u0.y; bf[2]=u1.x; bf[3]=u1.y;
            #pragma unroll
            for (int i = 0; i < 8; i++)
                #pragma unroll
                for (int j = 0; j < 4; j++)
                    s2[i][j] = fma2(a[i], bf[j], s2[i][j]);
        }

        // online softmax; columns c0..c3 = 2tx,2tx+1,32+2tx,33+2tx
        const float m0 = ms[2 * tx], m1 = ms[2 * tx + 1];
        const float m2 = ms[32 + 2 * tx], m3 = ms[33 + 2 * tx];
        #pragma unroll
        for (int i = 0; i < 8; i++) {
            float s[4];
            float lo, hi;
            unpack2(s2[i][0], lo, hi); s[0] = lo + hi + m0;
            unpack2(s2[i][1], lo, hi); s[1] = lo + hi + m1;
            unpack2(s2[i][2], lo, hi); s[2] = lo + hi + m2;
            unpack2(s2[i][3], lo, hi); s[3] = lo + hi + m3;

            float tmax = fmaxf(fmaxf(s[0], s[1]), fmaxf(s[2], s[3]));
            #pragma unroll
            for (int off = 1; off < 16; off <<= 1)
                tmax = fmaxf(tmax, __shfl_xor_sync(0xffffffffu, tmax, off));

            float mnew  = fmaxf(m_i[i], tmax);
            float alpha = __expf(m_i[i] - mnew);
            float p0 = __expf(s[0] - mnew);
            float p1 = __expf(s[1] - mnew);
            float p2 = __expf(s[2] - mnew);
            float p3 = __expf(s[3] - mnew);
            l_i[i] = l_i[i] * alpha + (p0 + p1) + (p2 + p3);
            m_i[i] = mnew;
            ull a2 = pack2(alpha, alpha);
            o2[i][0] = mul2(o2[i][0], a2);
            o2[i][1] = mul2(o2[i][1], a2);

            // Duplicated-pair stores, row-major: one 16B STS per c-half.
            // 16B-unit index = 33r + tx (+16) -> bank-group (i+tx)%8: spread.
            int r = ty * 8 + i;
            ull* pr = Psd + r * PSD_STRIDE;
            ulonglong2 w0, w1;
            w0.x = pack2(p0, p0); w0.y = pack2(p1, p1);
            w1.x = pack2(p2, p2); w1.y = pack2(p3, p3);
            *(ulonglong2*)(pr + 2 * tx)      = w0;
            *(ulonglong2*)(pr + 32 + 2 * tx) = w1;
        }

        // Prefetch next K/V tile (hidden behind barrier + GEMM2)
        if (kt + 1 < TT / 64) {
            const float* kn = kg + (size_t)(kt + 1) * 64 * DD;
            const float* vn = vg + (size_t)(kt + 1) * 64 * DD;
            #pragma unroll
            for (int i = 0; i < 4; i++) {
                int c = lrow + i * 16;
                kpre[i] = *(const float4*)(kn + (size_t)c * DD + lcol);
                vpre[i] = *(const float4*)(vn + (size_t)c * DD + lcol);
            }
        }
        __syncthreads();

        // GEMM2: O += P V over 2-c groups.
        //   q  = ulonglong2 broadcast: ((P(c),P(c)), (P(c+1),P(c+1)))
        //   vp = ulonglong2 lane-contiguous V row (2 d-pairs)
        //   All operands are natural aligned pairs -> no in-loop packing.
        #pragma unroll 2
        for (int cc = 0; cc < 32; cc++) {
            ulonglong2 vp0 = *(const ulonglong2*)(Vs + (2 * cc    ) * VS_STRIDE + 4 * tx);
            ulonglong2 vp1 = *(const ulonglong2*)(Vs + (2 * cc + 1) * VS_STRIDE + 4 * tx);
            const ull* pbase = Psd + (ty * 8) * PSD_STRIDE + 2 * cc;
            #pragma unroll
            for (int i = 0; i < 8; i++) {
                ulonglong2 q = *(const ulonglong2*)(pbase + i * PSD_STRIDE);
                o2[i][0] = fma2(q.x, vp0.x, o2[i][0]);
                o2[i][1] = fma2(q.x, vp0.y, o2[i][1]);
                o2[i][0] = fma2(q.y, vp1.x, o2[i][0]);
                o2[i][1] = fma2(q.y, vp1.y, o2[i][1]);
            }
        }
    }

    // Epilogue: reduce l over 16 lanes, scale, store.
    #pragma unroll
    for (int i = 0; i < 8; i++) {
        float lsum = l_i[i];
        #pragma unroll
        for (int off = 1; off < 16; off <<= 1)
            lsum += __shfl_xor_sync(0xffffffffu, lsum, off);
        float inv = 1.0f / lsum;
        float a0, a1, a2v, a3;
        unpack2(o2[i][0], a0, a1);
        unpack2(o2[i][1], a2v, a3);
        int r = ty * 8 + i;
        int t = qt * 128 + r;
        float4 v4 = make_float4(a0 * inv, a1 * inv, a2v * inv, a3 * inv);
        *(float4*)(out + ((size_t)(b * TT + t)) * PP + h * 64 + 4 * tx) = v4;
    }
}

// ---------------------------------------------------------------------------
extern "C" void kernel_launch(void* const* d_in, const int* in_sizes, int n_in,
                              void* d_out, int out_size) {
    const float* hs   = (const float*)d_in[0];
    const float* mask = (const float*)d_in[1];
    const float* Wq   = (const float*)d_in[2];
    const float* bq   = (const float*)d_in[3];
    const float* Wk   = (const float*)d_in[4];
    const float* bk   = (const float*)d_in[5];
    const float* Wv   = (const float*)d_in[6];
    const float* bv   = (const float*)d_in[7];
    float* out = (float*)d_out;

    qkv_proj_kernel<<<dim3((BB * TT) / 64, HH, 3), 128>>>(hs, Wq, bq, Wk, bk, Wv, bv);

    cudaFuncSetAttribute(flash_attn_kernel,
                         cudaFuncAttributeMaxDynamicSharedMemorySize, FLASH_SMEM);
    flash_attn_kernel<<<dim3(TT / 128, BB * HH), 256, FLASH_SMEM>>>(mask, out);
}